// round 14
// baseline (speedup 1.0000x reference)
#include <cuda_runtime.h>
#include <cuda_fp16.h>
#include <cstdint>
#include <cstddef>

// ===========================================================================
// TreeModel via single-pass fp16 HMMA GEMMs (fp32 accumulate).
// R13: R12 GEMM frozen; gate LOGITS stored fp16 (32MB instead of 64MB f32),
// sigmoid moved into tree kernel's smem fill.
// ===========================================================================

#define M_DIM   16384
#define K_DIM   1024
#define N_GATE  1023
#define N_OUT   1000

#define BM      128
#define BN      128
#define BK      64          // 64 fp16 = 128B rows (swizzled)
#define NCHUNKS 16          // 1024 / 64
#define STAGES  3

#define A_BYTES (BM * BK * 2)        // 16 KB
#define B_BYTES (BN * BK * 2)        // 16 KB
#define STG_BYTES (A_BYTES + B_BYTES)
#define TILES_BYTES (STAGES * STG_BYTES)          // 96 KB
#define SMEM_TOTAL  (TILES_BYTES + 64)

// ---- scratch (static device allocations) ----
__device__ __half  g_zh [(size_t)M_DIM * 1024];   // gate logits (fp16)
__device__ __half  g_xh [(size_t)M_DIM * 1024];   // fp16(x)
__device__ __half  g_ph [(size_t)M_DIM * 1024];   // fp16(probs)
__device__ __half  g_wh [1024 * 1024];            // W_gate^T fp16
__device__ __half  g_lh [1024 * 1024];            // leaf^T fp16

__device__ __forceinline__ uint32_t smem_u32(const void* p) {
    uint32_t a;
    asm("{ .reg .u64 t; cvta.to.shared.u64 t, %1; cvt.u32.u64 %0, t; }" : "=r"(a) : "l"(p));
    return a;
}
__device__ __forceinline__ void cp16(uint32_t saddr, const void* gaddr) {
    asm volatile("cp.async.cg.shared.global [%0], [%1], 16;" :: "r"(saddr), "l"(gaddr));
}
__device__ __forceinline__ void ldsm_x4(uint32_t& r0, uint32_t& r1, uint32_t& r2, uint32_t& r3,
                                        uint32_t addr) {
    asm volatile("ldmatrix.sync.aligned.m8n8.x4.shared.b16 {%0,%1,%2,%3}, [%4];"
                 : "=r"(r0), "=r"(r1), "=r"(r2), "=r"(r3) : "r"(addr));
}
__device__ __forceinline__ void mma16816(float* c, const uint32_t* a, uint32_t b0, uint32_t b1) {
    asm("mma.sync.aligned.m16n8k16.row.col.f32.f16.f16.f32 "
        "{%0,%1,%2,%3}, {%4,%5,%6,%7}, {%8,%9}, {%0,%1,%2,%3};"
        : "+f"(c[0]), "+f"(c[1]), "+f"(c[2]), "+f"(c[3])
        : "r"(a[0]), "r"(a[1]), "r"(a[2]), "r"(a[3]), "r"(b0), "r"(b1));
}

// ---- mbarrier helpers ----
#define MBAR_INIT(a, c) \
    asm volatile("mbarrier.init.shared.b64 [%0], %1;" :: "r"(a), "r"(c) : "memory")
#define MBAR_ARRIVE(a) \
    asm volatile("mbarrier.arrive.shared.b64 _, [%0];" :: "r"(a) : "memory")
#define CP_ASYNC_MBAR_ARRIVE(a) \
    asm volatile("cp.async.mbarrier.arrive.noinc.shared::cta.b64 [%0];" :: "r"(a) : "memory")
#define MBAR_WAIT(a, par) do {                                                   \
    uint32_t _m = (a); uint32_t _p = (par); uint32_t _d;                         \
    asm volatile("{\n\t.reg .pred p;\n\t"                                        \
        "mbarrier.try_wait.parity.acquire.cta.shared::cta.b64 p, [%1], %2;\n\t"  \
        "selp.b32 %0, 1, 0, p;\n\t}" : "=r"(_d) : "r"(_m), "r"(_p) : "memory");  \
    if (!_d) {                                                                   \
        asm volatile("{\n\t.reg .pred P1;\n\t"                                   \
            "WL_%=:\n\t"                                                         \
            "mbarrier.try_wait.parity.acquire.cta.shared::cta.b64 P1, [%0], %1, 0x989680;\n\t" \
            "@P1 bra.uni WD_%=;\n\t"                                             \
            "bra.uni WL_%=;\n\t"                                                 \
            "WD_%=:\n\t}" :: "r"(_m), "r"(_p) : "memory");                       \
    } } while (0)

// ---------------------------------------------------------------------------
// EPI=1: z = acc + bias -> fp16 C (ldc=1024)
// EPI=0: acc -> f32 C (ldc=N_OUT, guard col < N_OUT)
// ---------------------------------------------------------------------------
template<int EPI>
__global__ void __launch_bounds__(256, 2)
hmma_gemm(const __half* __restrict__ A, const __half* __restrict__ B,
          const float* __restrict__ bias, void* __restrict__ Cv)
{
    extern __shared__ char smem[];
    const uint32_t sbase = smem_u32(smem);
    const uint32_t mbase = sbase + TILES_BYTES;   // full[s] +s*16, empty[s] +s*16+8
    const int tid  = threadIdx.x;
    const int lane = tid & 31;
    const int wid  = tid >> 5;
    const int wm   = wid >> 1;          // 0..3
    const int wn   = wid & 1;           // 0..1
    const int m0w  = wm * 32;
    const int n0w  = wn * 64;
    const int bm0  = blockIdx.y * BM;
    const int bn0  = blockIdx.x * BN;

    if (tid == 0) {
        #pragma unroll
        for (int s = 0; s < STAGES; s++) {
            MBAR_INIT(mbase + s * 16, 256);       // full: 256 cp-group arrivals
            MBAR_INIT(mbase + s * 16 + 8, 256);   // empty: 256 thread arrivals
        }
    }
    __syncthreads();

    // ---- hoisted loader state: 4 swizzled smem offsets + 4 A ptrs + uniform delta
    uint32_t swOff[4];
    const char* gA[4];
    const ptrdiff_t bd = ((const char*)B - (const char*)A)
                       + (ptrdiff_t)(bn0 - bm0) * (K_DIM * 2);
    #pragma unroll
    for (int i = 0; i < 4; i++) {
        int idx = i * 256 + tid;                 // 0..1023
        int row = idx >> 3;                      // 0..127
        int ch  = idx & 7;                       // 16B chunk in row
        uint32_t col = (uint32_t)ch * 16;
        swOff[i] = (uint32_t)row * 128 + (col ^ (((uint32_t)row & 7u) << 4));
        gA[i] = (const char*)(A + (size_t)(bm0 + row) * K_DIM) + ch * 16;
    }

    // ldmatrix addressing: addr = rowBase + ((lh*16 + ks*32) ^ swmask)
    const int lr = lane & 15;
    const int lh = lane >> 4;
    const uint32_t sw = ((uint32_t)lr & 7u) << 4;
    uint32_t colX[4];
    #pragma unroll
    for (int ks = 0; ks < 4; ks++)
        colX[ks] = (((uint32_t)lh * 16) + (uint32_t)ks * 32) ^ sw;
    uint32_t aRow[2], bRow[4];
    #pragma unroll
    for (int mt = 0; mt < 2; mt++) aRow[mt] = (uint32_t)(m0w + mt * 16 + lr) * 128;
    #pragma unroll
    for (int p = 0; p < 4; p++)    bRow[p]  = (uint32_t)(n0w + p * 16 + lr) * 128;

    float acc[2][8][4];
    #pragma unroll
    for (int mt = 0; mt < 2; mt++)
        #pragma unroll
        for (int nt = 0; nt < 8; nt++)
            #pragma unroll
            for (int q = 0; q < 4; q++) acc[mt][nt][q] = 0.f;

    // producer cursor (stage 0, phase 1): first empty-waits pass immediately
    int pst = 0, pph = 1;
    #pragma unroll
    for (int pc = 0; pc < 2; pc++) {
        const uint32_t sa = sbase + (uint32_t)pst * STG_BYTES;
        const uint32_t sb = sa + A_BYTES;
        #pragma unroll
        for (int i = 0; i < 4; i++) {
            cp16(sa + swOff[i], gA[i]);
            cp16(sb + swOff[i], gA[i] + bd);
            gA[i] += BK * 2;
        }
        CP_ASYNC_MBAR_ARRIVE(mbase + pst * 16);
        if (++pst == STAGES) { pst = 0; pph ^= 1; }
    }

    int cst = 0, cph = 0;

    #pragma unroll 1
    for (int c = 0; c < NCHUNKS; c++) {
        MBAR_WAIT(mbase + cst * 16, (uint32_t)cph);          // stage cst full

        if (c + 2 < NCHUNKS) {
            MBAR_WAIT(mbase + pst * 16 + 8, (uint32_t)pph);  // stage pst empty
            const uint32_t sa = sbase + (uint32_t)pst * STG_BYTES;
            const uint32_t sb = sa + A_BYTES;
            #pragma unroll
            for (int i = 0; i < 4; i++) {
                cp16(sa + swOff[i], gA[i]);
                cp16(sb + swOff[i], gA[i] + bd);
                gA[i] += BK * 2;
            }
            CP_ASYNC_MBAR_ARRIVE(mbase + pst * 16);
            if (++pst == STAGES) { pst = 0; pph ^= 1; }
        }

        const uint32_t sa = sbase + (uint32_t)cst * STG_BYTES;
        const uint32_t sb = sa + A_BYTES;

        #pragma unroll
        for (int ks = 0; ks < 4; ks++) {
            uint32_t a[2][4];
            #pragma unroll
            for (int mt = 0; mt < 2; mt++)
                ldsm_x4(a[mt][0], a[mt][1], a[mt][2], a[mt][3], sa + aRow[mt] + colX[ks]);
            uint32_t b[8][2];
            #pragma unroll
            for (int p = 0; p < 4; p++) {
                uint32_t r0, r1, r2, r3;
                ldsm_x4(r0, r1, r2, r3, sb + bRow[p] + colX[ks]);
                b[p*2][0] = r0; b[p*2][1] = r2;
                b[p*2+1][0] = r1; b[p*2+1][1] = r3;
            }
            #pragma unroll
            for (int mt = 0; mt < 2; mt++)
                #pragma unroll
                for (int nt = 0; nt < 8; nt++)
                    mma16816(acc[mt][nt], a[mt], b[nt][0], b[nt][1]);
        }

        MBAR_ARRIVE(mbase + cst * 16 + 8);                   // done reading stage cst
        if (++cst == STAGES) { cst = 0; cph ^= 1; }
    }

    // epilogue
    const int gq = lane >> 2;
    const int tq = lane & 3;
    #pragma unroll
    for (int mt = 0; mt < 2; mt++) {
        #pragma unroll
        for (int nt = 0; nt < 8; nt++) {
            const int col = bn0 + n0w + nt * 8 + tq * 2;
            const int r0  = bm0 + m0w + mt * 16 + gq;
            float v0 = acc[mt][nt][0], v1 = acc[mt][nt][1];
            float v2 = acc[mt][nt][2], v3 = acc[mt][nt][3];
            if (EPI == 1) {
                // store logits z = acc + bias as fp16 (sigmoid applied in tree)
                __half* C = (__half*)Cv;
                float b0 = (col     < N_GATE) ? bias[col]     : 0.f;
                float b1 = (col + 1 < N_GATE) ? bias[col + 1] : 0.f;
                *(__half2*)(C + (size_t)r0 * 1024 + col) =
                    __floats2half2_rn(v0 + b0, v1 + b1);
                *(__half2*)(C + (size_t)(r0 + 8) * 1024 + col) =
                    __floats2half2_rn(v2 + b0, v3 + b1);
            } else {
                float* C = (float*)Cv;
                if (col + 1 < N_OUT) {
                    *(float2*)(C + (size_t)r0 * N_OUT + col)       = make_float2(v0, v1);
                    *(float2*)(C + (size_t)(r0 + 8) * N_OUT + col) = make_float2(v2, v3);
                } else if (col < N_OUT) {
                    C[(size_t)r0 * N_OUT + col]       = v0;
                    C[(size_t)(r0 + 8) * N_OUT + col] = v2;
                }
            }
        }
    }
}

// ---------------------------------------------------------------------------
// x: f32 -> fp16
// ---------------------------------------------------------------------------
__global__ void __launch_bounds__(256)
cvt_kernel(const float* __restrict__ in, __half* __restrict__ out, int n4)
{
    int i = blockIdx.x * 256 + threadIdx.x;
    if (i >= n4) return;
    float4 v = ((const float4*)in)[i];
    __half2* O = (__half2*)out;
    O[i*2]   = __floats2half2_rn(v.x, v.y);
    O[i*2+1] = __floats2half2_rn(v.z, v.w);
}

// ---------------------------------------------------------------------------
// transpose + convert: in[1024, Nin] f32 -> [1024(N, zero pad), 1024(K)] fp16
// ---------------------------------------------------------------------------
__global__ void __launch_bounds__(256)
transpose_cvt_kernel(const float* __restrict__ in, int Nin,
                     __half* __restrict__ outT)
{
    __shared__ float t[32][33];
    const int k0 = blockIdx.x * 32, n0 = blockIdx.y * 32;
    const int x = threadIdx.x & 31, y = threadIdx.x >> 5;
    #pragma unroll
    for (int i = 0; i < 32; i += 8) {
        int n = n0 + x;
        t[y + i][x] = (n < Nin) ? in[(size_t)(k0 + y + i) * Nin + n] : 0.f;
    }
    __syncthreads();
    #pragma unroll
    for (int i = 0; i < 32; i += 8) {
        int n = n0 + y + i, k = k0 + x;
        outT[(size_t)n * 1024 + k] = __float2half_rn(t[x][y + i]);
    }
}

// ---------------------------------------------------------------------------
// Tree path-product: sigmoid(fp16 logits) -> probs as fp16.
// ---------------------------------------------------------------------------
__global__ void __launch_bounds__(256)
tree_kernel()
{
    __shared__ float sp[2][1024];
    const int half = threadIdx.x >> 7;
    const int t    = threadIdx.x & 127;
    const int s    = blockIdx.x * 2 + half;

    const __half* zrow = g_zh + (size_t)s * 1024;
    #pragma unroll
    for (int i = 0; i < 8; i++) {
        int idx = t + i * 128;
        if (idx < N_GATE) {
            float z = __half2float(zrow[idx]);
            sp[half][idx] = 1.0f / (1.0f + __expf(-z));
        }
    }
    __syncthreads();

    const float* pr = sp[half];
    const int base = t * 8;

    float pref = 1.0f;
    #pragma unroll
    for (int k = 0; k < 7; k++) {
        int node = (1 << k) - 1 + (base >> (10 - k));
        int bit  = (base >> (9 - k)) & 1;
        float pv = pr[node];
        pref *= bit ? pv : (1.0f - pv);
    }
    float p7 = pr[127 + (base >> 3)];
    float p8[2];
    p8[0] = pr[255 + (base >> 2) + 0];
    p8[1] = pr[255 + (base >> 2) + 1];
    float p9[4];
    #pragma unroll
    for (int i = 0; i < 4; i++) p9[i] = pr[511 + (base >> 1) + i];

    __align__(16) __half H[8];
    #pragma unroll
    for (int j = 0; j < 8; j++) {
        int b2 = (j >> 2) & 1, b1 = (j >> 1) & 1, b0 = j & 1;
        float v = pref * (b2 ? p7 : (1.0f - p7));
        float q8 = p8[b2];
        v *= b1 ? q8 : (1.0f - q8);
        float q9 = p9[j >> 1];
        v *= b0 ? q9 : (1.0f - q9);
        H[j] = __float2half_rn(v);
    }
    *(uint4*)(g_ph + (size_t)s * 1024 + base) = *(uint4*)H;
}

// ---------------------------------------------------------------------------
extern "C" void kernel_launch(void* const* d_in, const int* in_sizes, int n_in,
                              void* d_out, int out_size)
{
    const float* x    = (const float*)d_in[0];
    const float* Wg   = (const float*)d_in[1];
    const float* bg   = (const float*)d_in[2];
    const float* leaf = (const float*)d_in[3];
    float* out = (float*)d_out;

    __half *zh, *xh, *ph, *wh, *lh;
    cudaGetSymbolAddress((void**)&zh, g_zh);
    cudaGetSymbolAddress((void**)&xh, g_xh);
    cudaGetSymbolAddress((void**)&ph, g_ph);
    cudaGetSymbolAddress((void**)&wh, g_wh);
    cudaGetSymbolAddress((void**)&lh, g_lh);

    cudaFuncSetAttribute(hmma_gemm<1>, cudaFuncAttributeMaxDynamicSharedMemorySize, SMEM_TOTAL);
    cudaFuncSetAttribute(hmma_gemm<0>, cudaFuncAttributeMaxDynamicSharedMemorySize, SMEM_TOTAL);

    // prep: convert x; transpose+convert weights
    {
        int n4 = (M_DIM * K_DIM) / 4;
        cvt_kernel<<<(n4 + 255) / 256, 256>>>(x, xh, n4);
        dim3 tg(32, 32);
        transpose_cvt_kernel<<<tg, 256>>>(Wg, N_GATE, wh);
        transpose_cvt_kernel<<<tg, 256>>>(leaf, N_OUT, lh);
    }

    // GEMM1 -> fp16 logits g_zh
    {
        dim3 grid(1024 / BN, M_DIM / BM);   // (8, 128)
        hmma_gemm<1><<<grid, 256, SMEM_TOTAL>>>(xh, wh, bg, zh);
    }

    // tree: sigmoid + path products -> probs fp16
    tree_kernel<<<M_DIM / 2, 256>>>();

    // GEMM2 -> out
    {
        dim3 grid(1024 / BN, M_DIM / BM);   // (8, 128)
        hmma_gemm<0><<<grid, 256, SMEM_TOTAL>>>(ph, lh, nullptr, out);
    }
}

// round 15
// speedup vs baseline: 1.0328x; 1.0328x over previous
#include <cuda_runtime.h>
#include <cuda_fp16.h>
#include <cstdint>
#include <cstddef>

// ===========================================================================
// TreeModel via single-pass fp16 HMMA GEMMs (fp32 accumulate).
// R14: R12 GEMM + numerics (f32 gate probs, sigmoid in GEMM1 epilogue),
// prep (cvt + both transposes) fused into ONE kernel launch.
// ===========================================================================

#define M_DIM   16384
#define K_DIM   1024
#define N_GATE  1023
#define N_OUT   1000

#define BM      128
#define BN      128
#define BK      64          // 64 fp16 = 128B rows (swizzled)
#define NCHUNKS 16          // 1024 / 64
#define STAGES  3

#define A_BYTES (BM * BK * 2)        // 16 KB
#define B_BYTES (BN * BK * 2)        // 16 KB
#define STG_BYTES (A_BYTES + B_BYTES)
#define TILES_BYTES (STAGES * STG_BYTES)          // 96 KB
#define SMEM_TOTAL  (TILES_BYTES + 64)

// ---- scratch (static device allocations) ----
__device__ float   g_p  [(size_t)M_DIM * 1024];   // gate probabilities (f32)
__device__ __half  g_xh [(size_t)M_DIM * 1024];   // fp16(x)
__device__ __half  g_ph [(size_t)M_DIM * 1024];   // fp16(probs)
__device__ __half  g_wh [1024 * 1024];            // W_gate^T fp16
__device__ __half  g_lh [1024 * 1024];            // leaf^T fp16

__device__ __forceinline__ uint32_t smem_u32(const void* p) {
    uint32_t a;
    asm("{ .reg .u64 t; cvta.to.shared.u64 t, %1; cvt.u32.u64 %0, t; }" : "=r"(a) : "l"(p));
    return a;
}
__device__ __forceinline__ void cp16(uint32_t saddr, const void* gaddr) {
    asm volatile("cp.async.cg.shared.global [%0], [%1], 16;" :: "r"(saddr), "l"(gaddr));
}
__device__ __forceinline__ void ldsm_x4(uint32_t& r0, uint32_t& r1, uint32_t& r2, uint32_t& r3,
                                        uint32_t addr) {
    asm volatile("ldmatrix.sync.aligned.m8n8.x4.shared.b16 {%0,%1,%2,%3}, [%4];"
                 : "=r"(r0), "=r"(r1), "=r"(r2), "=r"(r3) : "r"(addr));
}
__device__ __forceinline__ void mma16816(float* c, const uint32_t* a, uint32_t b0, uint32_t b1) {
    asm("mma.sync.aligned.m16n8k16.row.col.f32.f16.f16.f32 "
        "{%0,%1,%2,%3}, {%4,%5,%6,%7}, {%8,%9}, {%0,%1,%2,%3};"
        : "+f"(c[0]), "+f"(c[1]), "+f"(c[2]), "+f"(c[3])
        : "r"(a[0]), "r"(a[1]), "r"(a[2]), "r"(a[3]), "r"(b0), "r"(b1));
}

// ---- mbarrier helpers ----
#define MBAR_INIT(a, c) \
    asm volatile("mbarrier.init.shared.b64 [%0], %1;" :: "r"(a), "r"(c) : "memory")
#define MBAR_ARRIVE(a) \
    asm volatile("mbarrier.arrive.shared.b64 _, [%0];" :: "r"(a) : "memory")
#define CP_ASYNC_MBAR_ARRIVE(a) \
    asm volatile("cp.async.mbarrier.arrive.noinc.shared::cta.b64 [%0];" :: "r"(a) : "memory")
#define MBAR_WAIT(a, par) do {                                                   \
    uint32_t _m = (a); uint32_t _p = (par); uint32_t _d;                         \
    asm volatile("{\n\t.reg .pred p;\n\t"                                        \
        "mbarrier.try_wait.parity.acquire.cta.shared::cta.b64 p, [%1], %2;\n\t"  \
        "selp.b32 %0, 1, 0, p;\n\t}" : "=r"(_d) : "r"(_m), "r"(_p) : "memory");  \
    if (!_d) {                                                                   \
        asm volatile("{\n\t.reg .pred P1;\n\t"                                   \
            "WL_%=:\n\t"                                                         \
            "mbarrier.try_wait.parity.acquire.cta.shared::cta.b64 P1, [%0], %1, 0x989680;\n\t" \
            "@P1 bra.uni WD_%=;\n\t"                                             \
            "bra.uni WL_%=;\n\t"                                                 \
            "WD_%=:\n\t}" :: "r"(_m), "r"(_p) : "memory");                       \
    } } while (0)

// ---------------------------------------------------------------------------
// EPI=1: sigmoid(acc + bias) -> f32 C (ldc=1024)
// EPI=0: acc -> f32 C (ldc=N_OUT, guard col < N_OUT)
// ---------------------------------------------------------------------------
template<int EPI>
__global__ void __launch_bounds__(256, 2)
hmma_gemm(const __half* __restrict__ A, const __half* __restrict__ B,
          const float* __restrict__ bias, float* __restrict__ C)
{
    extern __shared__ char smem[];
    const uint32_t sbase = smem_u32(smem);
    const uint32_t mbase = sbase + TILES_BYTES;   // full[s] +s*16, empty[s] +s*16+8
    const int tid  = threadIdx.x;
    const int lane = tid & 31;
    const int wid  = tid >> 5;
    const int wm   = wid >> 1;          // 0..3
    const int wn   = wid & 1;           // 0..1
    const int m0w  = wm * 32;
    const int n0w  = wn * 64;
    const int bm0  = blockIdx.y * BM;
    const int bn0  = blockIdx.x * BN;

    if (tid == 0) {
        #pragma unroll
        for (int s = 0; s < STAGES; s++) {
            MBAR_INIT(mbase + s * 16, 256);       // full: 256 cp-group arrivals
            MBAR_INIT(mbase + s * 16 + 8, 256);   // empty: 256 thread arrivals
        }
    }
    __syncthreads();

    // ---- hoisted loader state: 4 swizzled smem offsets + 4 A ptrs + uniform delta
    uint32_t swOff[4];
    const char* gA[4];
    const ptrdiff_t bd = ((const char*)B - (const char*)A)
                       + (ptrdiff_t)(bn0 - bm0) * (K_DIM * 2);
    #pragma unroll
    for (int i = 0; i < 4; i++) {
        int idx = i * 256 + tid;                 // 0..1023
        int row = idx >> 3;                      // 0..127
        int ch  = idx & 7;                       // 16B chunk in row
        uint32_t col = (uint32_t)ch * 16;
        swOff[i] = (uint32_t)row * 128 + (col ^ (((uint32_t)row & 7u) << 4));
        gA[i] = (const char*)(A + (size_t)(bm0 + row) * K_DIM) + ch * 16;
    }

    // ldmatrix addressing: addr = rowBase + ((lh*16 + ks*32) ^ swmask)
    const int lr = lane & 15;
    const int lh = lane >> 4;
    const uint32_t sw = ((uint32_t)lr & 7u) << 4;
    uint32_t colX[4];
    #pragma unroll
    for (int ks = 0; ks < 4; ks++)
        colX[ks] = (((uint32_t)lh * 16) + (uint32_t)ks * 32) ^ sw;
    uint32_t aRow[2], bRow[4];
    #pragma unroll
    for (int mt = 0; mt < 2; mt++) aRow[mt] = (uint32_t)(m0w + mt * 16 + lr) * 128;
    #pragma unroll
    for (int p = 0; p < 4; p++)    bRow[p]  = (uint32_t)(n0w + p * 16 + lr) * 128;

    float acc[2][8][4];
    #pragma unroll
    for (int mt = 0; mt < 2; mt++)
        #pragma unroll
        for (int nt = 0; nt < 8; nt++)
            #pragma unroll
            for (int q = 0; q < 4; q++) acc[mt][nt][q] = 0.f;

    // producer cursor (stage 0, phase 1): first empty-waits pass immediately
    int pst = 0, pph = 1;
    #pragma unroll
    for (int pc = 0; pc < 2; pc++) {
        const uint32_t sa = sbase + (uint32_t)pst * STG_BYTES;
        const uint32_t sb = sa + A_BYTES;
        #pragma unroll
        for (int i = 0; i < 4; i++) {
            cp16(sa + swOff[i], gA[i]);
            cp16(sb + swOff[i], gA[i] + bd);
            gA[i] += BK * 2;
        }
        CP_ASYNC_MBAR_ARRIVE(mbase + pst * 16);
        if (++pst == STAGES) { pst = 0; pph ^= 1; }
    }

    int cst = 0, cph = 0;

    #pragma unroll 1
    for (int c = 0; c < NCHUNKS; c++) {
        MBAR_WAIT(mbase + cst * 16, (uint32_t)cph);          // stage cst full

        if (c + 2 < NCHUNKS) {
            MBAR_WAIT(mbase + pst * 16 + 8, (uint32_t)pph);  // stage pst empty
            const uint32_t sa = sbase + (uint32_t)pst * STG_BYTES;
            const uint32_t sb = sa + A_BYTES;
            #pragma unroll
            for (int i = 0; i < 4; i++) {
                cp16(sa + swOff[i], gA[i]);
                cp16(sb + swOff[i], gA[i] + bd);
                gA[i] += BK * 2;
            }
            CP_ASYNC_MBAR_ARRIVE(mbase + pst * 16);
            if (++pst == STAGES) { pst = 0; pph ^= 1; }
        }

        const uint32_t sa = sbase + (uint32_t)cst * STG_BYTES;
        const uint32_t sb = sa + A_BYTES;

        #pragma unroll
        for (int ks = 0; ks < 4; ks++) {
            uint32_t a[2][4];
            #pragma unroll
            for (int mt = 0; mt < 2; mt++)
                ldsm_x4(a[mt][0], a[mt][1], a[mt][2], a[mt][3], sa + aRow[mt] + colX[ks]);
            uint32_t b[8][2];
            #pragma unroll
            for (int p = 0; p < 4; p++) {
                uint32_t r0, r1, r2, r3;
                ldsm_x4(r0, r1, r2, r3, sb + bRow[p] + colX[ks]);
                b[p*2][0] = r0; b[p*2][1] = r2;
                b[p*2+1][0] = r1; b[p*2+1][1] = r3;
            }
            #pragma unroll
            for (int mt = 0; mt < 2; mt++)
                #pragma unroll
                for (int nt = 0; nt < 8; nt++)
                    mma16816(acc[mt][nt], a[mt], b[nt][0], b[nt][1]);
        }

        MBAR_ARRIVE(mbase + cst * 16 + 8);                   // done reading stage cst
        if (++cst == STAGES) { cst = 0; cph ^= 1; }
    }

    // epilogue
    const int gq = lane >> 2;
    const int tq = lane & 3;
    #pragma unroll
    for (int mt = 0; mt < 2; mt++) {
        #pragma unroll
        for (int nt = 0; nt < 8; nt++) {
            const int col = bn0 + n0w + nt * 8 + tq * 2;
            const int r0  = bm0 + m0w + mt * 16 + gq;
            float v0 = acc[mt][nt][0], v1 = acc[mt][nt][1];
            float v2 = acc[mt][nt][2], v3 = acc[mt][nt][3];
            if (EPI == 1) {
                float b0 = (col     < N_GATE) ? bias[col]     : 0.f;
                float b1 = (col + 1 < N_GATE) ? bias[col + 1] : 0.f;
                v0 = 1.f / (1.f + __expf(-(v0 + b0)));
                v1 = 1.f / (1.f + __expf(-(v1 + b1)));
                v2 = 1.f / (1.f + __expf(-(v2 + b0)));
                v3 = 1.f / (1.f + __expf(-(v3 + b1)));
                *(float2*)(C + (size_t)r0 * 1024 + col)       = make_float2(v0, v1);
                *(float2*)(C + (size_t)(r0 + 8) * 1024 + col) = make_float2(v2, v3);
            } else {
                if (col + 1 < N_OUT) {
                    *(float2*)(C + (size_t)r0 * N_OUT + col)       = make_float2(v0, v1);
                    *(float2*)(C + (size_t)(r0 + 8) * N_OUT + col) = make_float2(v2, v3);
                } else if (col < N_OUT) {
                    C[(size_t)r0 * N_OUT + col]       = v0;
                    C[(size_t)(r0 + 8) * N_OUT + col] = v2;
                }
            }
        }
    }
}

// ---------------------------------------------------------------------------
// Fused prep: blocks [0, CVT_BLKS): x f32->fp16
//             [CVT_BLKS, +1024): transpose+cvt W_gate
//             [CVT_BLKS+1024, +2048): transpose+cvt leaf_logits
// ---------------------------------------------------------------------------
#define CVT_BLKS ((M_DIM * K_DIM / 4) / 256)   // 16384

__global__ void __launch_bounds__(256)
prep_kernel(const float* __restrict__ x,
            const float* __restrict__ Wg,
            const float* __restrict__ leaf,
            __half* __restrict__ xh,
            __half* __restrict__ wh,
            __half* __restrict__ lh)
{
    __shared__ float t[32][33];
    const int b = blockIdx.x;

    if (b < CVT_BLKS) {
        int i = b * 256 + threadIdx.x;
        float4 v = ((const float4*)x)[i];
        __half2* O = (__half2*)xh;
        O[i*2]   = __floats2half2_rn(v.x, v.y);
        O[i*2+1] = __floats2half2_rn(v.z, v.w);
        return;
    }

    // transpose job
    const int tb   = b - CVT_BLKS;          // 0..2047
    const int job  = tb >> 10;              // 0: W, 1: leaf
    const int lb   = tb & 1023;
    const float* in  = job ? leaf : Wg;
    __half* outT     = job ? lh : wh;
    const int Nin    = job ? N_OUT : N_GATE;

    const int k0 = (lb & 31) * 32, n0 = (lb >> 5) * 32;
    const int xx = threadIdx.x & 31, yy = threadIdx.x >> 5;
    #pragma unroll
    for (int i = 0; i < 32; i += 8) {
        int n = n0 + xx;
        t[yy + i][xx] = (n < Nin) ? in[(size_t)(k0 + yy + i) * Nin + n] : 0.f;
    }
    __syncthreads();
    #pragma unroll
    for (int i = 0; i < 32; i += 8) {
        int n = n0 + yy + i, k = k0 + xx;
        outT[(size_t)n * 1024 + k] = __float2half_rn(t[xx][yy + i]);
    }
}

// ---------------------------------------------------------------------------
// Tree path-product -> probs as fp16.
// ---------------------------------------------------------------------------
__global__ void __launch_bounds__(256)
tree_kernel()
{
    __shared__ float sp[2][1024];
    const int half = threadIdx.x >> 7;
    const int t    = threadIdx.x & 127;
    const int s    = blockIdx.x * 2 + half;

    const float* prow = g_p + (size_t)s * 1024;
    #pragma unroll
    for (int i = 0; i < 8; i++) {
        int idx = t + i * 128;
        if (idx < N_GATE) sp[half][idx] = prow[idx];
    }
    __syncthreads();

    const float* pr = sp[half];
    const int base = t * 8;

    float pref = 1.0f;
    #pragma unroll
    for (int k = 0; k < 7; k++) {
        int node = (1 << k) - 1 + (base >> (10 - k));
        int bit  = (base >> (9 - k)) & 1;
        float pv = pr[node];
        pref *= bit ? pv : (1.0f - pv);
    }
    float p7 = pr[127 + (base >> 3)];
    float p8[2];
    p8[0] = pr[255 + (base >> 2) + 0];
    p8[1] = pr[255 + (base >> 2) + 1];
    float p9[4];
    #pragma unroll
    for (int i = 0; i < 4; i++) p9[i] = pr[511 + (base >> 1) + i];

    __align__(16) __half H[8];
    #pragma unroll
    for (int j = 0; j < 8; j++) {
        int b2 = (j >> 2) & 1, b1 = (j >> 1) & 1, b0 = j & 1;
        float v = pref * (b2 ? p7 : (1.0f - p7));
        float q8 = p8[b2];
        v *= b1 ? q8 : (1.0f - q8);
        float q9 = p9[j >> 1];
        v *= b0 ? q9 : (1.0f - q9);
        H[j] = __float2half_rn(v);
    }
    *(uint4*)(g_ph + (size_t)s * 1024 + base) = *(uint4*)H;
}

// ---------------------------------------------------------------------------
extern "C" void kernel_launch(void* const* d_in, const int* in_sizes, int n_in,
                              void* d_out, int out_size)
{
    const float* x    = (const float*)d_in[0];
    const float* Wg   = (const float*)d_in[1];
    const float* bg   = (const float*)d_in[2];
    const float* leaf = (const float*)d_in[3];
    float* out = (float*)d_out;

    float *p_ptr;
    __half *xh, *ph, *wh, *lh;
    cudaGetSymbolAddress((void**)&p_ptr, g_p);
    cudaGetSymbolAddress((void**)&xh, g_xh);
    cudaGetSymbolAddress((void**)&ph, g_ph);
    cudaGetSymbolAddress((void**)&wh, g_wh);
    cudaGetSymbolAddress((void**)&lh, g_lh);

    cudaFuncSetAttribute(hmma_gemm<1>, cudaFuncAttributeMaxDynamicSharedMemorySize, SMEM_TOTAL);
    cudaFuncSetAttribute(hmma_gemm<0>, cudaFuncAttributeMaxDynamicSharedMemorySize, SMEM_TOTAL);

    // fused prep: convert x + transpose/convert both weight matrices
    prep_kernel<<<CVT_BLKS + 2048, 256>>>(x, Wg, leaf, xh, wh, lh);

    // GEMM1 + sigmoid -> g_p
    {
        dim3 grid(1024 / BN, M_DIM / BM);   // (8, 128)
        hmma_gemm<1><<<grid, 256, SMEM_TOTAL>>>(xh, wh, bg, p_ptr);
    }

    // tree products -> probs fp16
    tree_kernel<<<M_DIM / 2, 256>>>();

    // GEMM2 -> out
    {
        dim3 grid(1024 / BN, M_DIM / BM);   // (8, 128)
        hmma_gemm<0><<<grid, 256, SMEM_TOTAL>>>(ph, lh, nullptr, out);
    }
}

// round 16
// speedup vs baseline: 1.0339x; 1.0011x over previous
#include <cuda_runtime.h>
#include <cuda_fp16.h>
#include <cstdint>
#include <cstddef>

// ===========================================================================
// TreeModel via single-pass fp16 HMMA GEMMs (fp32 accumulate).
// R15: R14 + elected per-warp empty-barrier arrives (count 8 instead of 256)
// to cut per-chunk barrier issue traffic.
// ===========================================================================

#define M_DIM   16384
#define K_DIM   1024
#define N_GATE  1023
#define N_OUT   1000

#define BM      128
#define BN      128
#define BK      64          // 64 fp16 = 128B rows (swizzled)
#define NCHUNKS 16          // 1024 / 64
#define STAGES  3

#define A_BYTES (BM * BK * 2)        // 16 KB
#define B_BYTES (BN * BK * 2)        // 16 KB
#define STG_BYTES (A_BYTES + B_BYTES)
#define TILES_BYTES (STAGES * STG_BYTES)          // 96 KB
#define SMEM_TOTAL  (TILES_BYTES + 64)

// ---- scratch (static device allocations) ----
__device__ float   g_p  [(size_t)M_DIM * 1024];   // gate probabilities (f32)
__device__ __half  g_xh [(size_t)M_DIM * 1024];   // fp16(x)
__device__ __half  g_ph [(size_t)M_DIM * 1024];   // fp16(probs)
__device__ __half  g_wh [1024 * 1024];            // W_gate^T fp16
__device__ __half  g_lh [1024 * 1024];            // leaf^T fp16

__device__ __forceinline__ uint32_t smem_u32(const void* p) {
    uint32_t a;
    asm("{ .reg .u64 t; cvta.to.shared.u64 t, %1; cvt.u32.u64 %0, t; }" : "=r"(a) : "l"(p));
    return a;
}
__device__ __forceinline__ uint32_t elect_one() {
    uint32_t r;
    asm volatile("{\n\t.reg .pred p;\n\telect.sync _|p, 0xFFFFFFFF;\n\tselp.b32 %0, 1, 0, p;\n\t}" : "=r"(r));
    return r;
}
__device__ __forceinline__ void cp16(uint32_t saddr, const void* gaddr) {
    asm volatile("cp.async.cg.shared.global [%0], [%1], 16;" :: "r"(saddr), "l"(gaddr));
}
__device__ __forceinline__ void ldsm_x4(uint32_t& r0, uint32_t& r1, uint32_t& r2, uint32_t& r3,
                                        uint32_t addr) {
    asm volatile("ldmatrix.sync.aligned.m8n8.x4.shared.b16 {%0,%1,%2,%3}, [%4];"
                 : "=r"(r0), "=r"(r1), "=r"(r2), "=r"(r3) : "r"(addr));
}
__device__ __forceinline__ void mma16816(float* c, const uint32_t* a, uint32_t b0, uint32_t b1) {
    asm("mma.sync.aligned.m16n8k16.row.col.f32.f16.f16.f32 "
        "{%0,%1,%2,%3}, {%4,%5,%6,%7}, {%8,%9}, {%0,%1,%2,%3};"
        : "+f"(c[0]), "+f"(c[1]), "+f"(c[2]), "+f"(c[3])
        : "r"(a[0]), "r"(a[1]), "r"(a[2]), "r"(a[3]), "r"(b0), "r"(b1));
}

// ---- mbarrier helpers ----
#define MBAR_INIT(a, c) \
    asm volatile("mbarrier.init.shared.b64 [%0], %1;" :: "r"(a), "r"(c) : "memory")
#define MBAR_ARRIVE(a) \
    asm volatile("mbarrier.arrive.shared.b64 _, [%0];" :: "r"(a) : "memory")
#define CP_ASYNC_MBAR_ARRIVE(a) \
    asm volatile("cp.async.mbarrier.arrive.noinc.shared::cta.b64 [%0];" :: "r"(a) : "memory")
#define MBAR_WAIT(a, par) do {                                                   \
    uint32_t _m = (a); uint32_t _p = (par); uint32_t _d;                         \
    asm volatile("{\n\t.reg .pred p;\n\t"                                        \
        "mbarrier.try_wait.parity.acquire.cta.shared::cta.b64 p, [%1], %2;\n\t"  \
        "selp.b32 %0, 1, 0, p;\n\t}" : "=r"(_d) : "r"(_m), "r"(_p) : "memory");  \
    if (!_d) {                                                                   \
        asm volatile("{\n\t.reg .pred P1;\n\t"                                   \
            "WL_%=:\n\t"                                                         \
            "mbarrier.try_wait.parity.acquire.cta.shared::cta.b64 P1, [%0], %1, 0x989680;\n\t" \
            "@P1 bra.uni WD_%=;\n\t"                                             \
            "bra.uni WL_%=;\n\t"                                                 \
            "WD_%=:\n\t}" :: "r"(_m), "r"(_p) : "memory");                       \
    } } while (0)

// ---------------------------------------------------------------------------
// EPI=1: sigmoid(acc + bias) -> f32 C (ldc=1024)
// EPI=0: acc -> f32 C (ldc=N_OUT, guard col < N_OUT)
// ---------------------------------------------------------------------------
template<int EPI>
__global__ void __launch_bounds__(256, 2)
hmma_gemm(const __half* __restrict__ A, const __half* __restrict__ B,
          const float* __restrict__ bias, float* __restrict__ C)
{
    extern __shared__ char smem[];
    const uint32_t sbase = smem_u32(smem);
    const uint32_t mbase = sbase + TILES_BYTES;   // full[s] +s*16, empty[s] +s*16+8
    const int tid  = threadIdx.x;
    const int lane = tid & 31;
    const int wid  = tid >> 5;
    const int wm   = wid >> 1;          // 0..3
    const int wn   = wid & 1;           // 0..1
    const int m0w  = wm * 32;
    const int n0w  = wn * 64;
    const int bm0  = blockIdx.y * BM;
    const int bn0  = blockIdx.x * BN;

    if (tid == 0) {
        #pragma unroll
        for (int s = 0; s < STAGES; s++) {
            MBAR_INIT(mbase + s * 16, 256);       // full: 256 cp-group arrivals
            MBAR_INIT(mbase + s * 16 + 8, 8);     // empty: 8 per-warp arrivals
        }
    }
    __syncthreads();

    // ---- hoisted loader state: 4 swizzled smem offsets + 4 A ptrs + uniform delta
    uint32_t swOff[4];
    const char* gA[4];
    const ptrdiff_t bd = ((const char*)B - (const char*)A)
                       + (ptrdiff_t)(bn0 - bm0) * (K_DIM * 2);
    #pragma unroll
    for (int i = 0; i < 4; i++) {
        int idx = i * 256 + tid;                 // 0..1023
        int row = idx >> 3;                      // 0..127
        int ch  = idx & 7;                       // 16B chunk in row
        uint32_t col = (uint32_t)ch * 16;
        swOff[i] = (uint32_t)row * 128 + (col ^ (((uint32_t)row & 7u) << 4));
        gA[i] = (const char*)(A + (size_t)(bm0 + row) * K_DIM) + ch * 16;
    }

    // ldmatrix addressing: addr = rowBase + ((lh*16 + ks*32) ^ swmask)
    const int lr = lane & 15;
    const int lh = lane >> 4;
    const uint32_t sw = ((uint32_t)lr & 7u) << 4;
    uint32_t colX[4];
    #pragma unroll
    for (int ks = 0; ks < 4; ks++)
        colX[ks] = (((uint32_t)lh * 16) + (uint32_t)ks * 32) ^ sw;
    uint32_t aRow[2], bRow[4];
    #pragma unroll
    for (int mt = 0; mt < 2; mt++) aRow[mt] = (uint32_t)(m0w + mt * 16 + lr) * 128;
    #pragma unroll
    for (int p = 0; p < 4; p++)    bRow[p]  = (uint32_t)(n0w + p * 16 + lr) * 128;

    float acc[2][8][4];
    #pragma unroll
    for (int mt = 0; mt < 2; mt++)
        #pragma unroll
        for (int nt = 0; nt < 8; nt++)
            #pragma unroll
            for (int q = 0; q < 4; q++) acc[mt][nt][q] = 0.f;

    // producer cursor (stage 0, phase 1): first empty-waits pass immediately
    int pst = 0, pph = 1;
    #pragma unroll
    for (int pc = 0; pc < 2; pc++) {
        const uint32_t sa = sbase + (uint32_t)pst * STG_BYTES;
        const uint32_t sb = sa + A_BYTES;
        #pragma unroll
        for (int i = 0; i < 4; i++) {
            cp16(sa + swOff[i], gA[i]);
            cp16(sb + swOff[i], gA[i] + bd);
            gA[i] += BK * 2;
        }
        CP_ASYNC_MBAR_ARRIVE(mbase + pst * 16);
        if (++pst == STAGES) { pst = 0; pph ^= 1; }
    }

    int cst = 0, cph = 0;

    #pragma unroll 1
    for (int c = 0; c < NCHUNKS; c++) {
        MBAR_WAIT(mbase + cst * 16, (uint32_t)cph);          // stage cst full

        if (c + 2 < NCHUNKS) {
            MBAR_WAIT(mbase + pst * 16 + 8, (uint32_t)pph);  // stage pst empty
            const uint32_t sa = sbase + (uint32_t)pst * STG_BYTES;
            const uint32_t sb = sa + A_BYTES;
            #pragma unroll
            for (int i = 0; i < 4; i++) {
                cp16(sa + swOff[i], gA[i]);
                cp16(sb + swOff[i], gA[i] + bd);
                gA[i] += BK * 2;
            }
            CP_ASYNC_MBAR_ARRIVE(mbase + pst * 16);
            if (++pst == STAGES) { pst = 0; pph ^= 1; }
        }

        const uint32_t sa = sbase + (uint32_t)cst * STG_BYTES;
        const uint32_t sb = sa + A_BYTES;

        #pragma unroll
        for (int ks = 0; ks < 4; ks++) {
            uint32_t a[2][4];
            #pragma unroll
            for (int mt = 0; mt < 2; mt++)
                ldsm_x4(a[mt][0], a[mt][1], a[mt][2], a[mt][3], sa + aRow[mt] + colX[ks]);
            uint32_t b[8][2];
            #pragma unroll
            for (int p = 0; p < 4; p++) {
                uint32_t r0, r1, r2, r3;
                ldsm_x4(r0, r1, r2, r3, sb + bRow[p] + colX[ks]);
                b[p*2][0] = r0; b[p*2][1] = r2;
                b[p*2+1][0] = r1; b[p*2+1][1] = r3;
            }
            #pragma unroll
            for (int mt = 0; mt < 2; mt++)
                #pragma unroll
                for (int nt = 0; nt < 8; nt++)
                    mma16816(acc[mt][nt], a[mt], b[nt][0], b[nt][1]);
        }

        // warp-synchronous at this point: one elected arrive per warp
        if (elect_one())
            MBAR_ARRIVE(mbase + cst * 16 + 8);               // done reading stage cst
        if (++cst == STAGES) { cst = 0; cph ^= 1; }
    }

    // epilogue
    const int gq = lane >> 2;
    const int tq = lane & 3;
    #pragma unroll
    for (int mt = 0; mt < 2; mt++) {
        #pragma unroll
        for (int nt = 0; nt < 8; nt++) {
            const int col = bn0 + n0w + nt * 8 + tq * 2;
            const int r0  = bm0 + m0w + mt * 16 + gq;
            float v0 = acc[mt][nt][0], v1 = acc[mt][nt][1];
            float v2 = acc[mt][nt][2], v3 = acc[mt][nt][3];
            if (EPI == 1) {
                float b0 = (col     < N_GATE) ? bias[col]     : 0.f;
                float b1 = (col + 1 < N_GATE) ? bias[col + 1] : 0.f;
                v0 = 1.f / (1.f + __expf(-(v0 + b0)));
                v1 = 1.f / (1.f + __expf(-(v1 + b1)));
                v2 = 1.f / (1.f + __expf(-(v2 + b0)));
                v3 = 1.f / (1.f + __expf(-(v3 + b1)));
                *(float2*)(C + (size_t)r0 * 1024 + col)       = make_float2(v0, v1);
                *(float2*)(C + (size_t)(r0 + 8) * 1024 + col) = make_float2(v2, v3);
            } else {
                if (col + 1 < N_OUT) {
                    *(float2*)(C + (size_t)r0 * N_OUT + col)       = make_float2(v0, v1);
                    *(float2*)(C + (size_t)(r0 + 8) * N_OUT + col) = make_float2(v2, v3);
                } else if (col < N_OUT) {
                    C[(size_t)r0 * N_OUT + col]       = v0;
                    C[(size_t)(r0 + 8) * N_OUT + col] = v2;
                }
            }
        }
    }
}

// ---------------------------------------------------------------------------
// Fused prep: blocks [0, CVT_BLKS): x f32->fp16
//             [CVT_BLKS, +1024): transpose+cvt W_gate
//             [CVT_BLKS+1024, +2048): transpose+cvt leaf_logits
// ---------------------------------------------------------------------------
#define CVT_BLKS ((M_DIM * K_DIM / 4) / 256)   // 16384

__global__ void __launch_bounds__(256)
prep_kernel(const float* __restrict__ x,
            const float* __restrict__ Wg,
            const float* __restrict__ leaf,
            __half* __restrict__ xh,
            __half* __restrict__ wh,
            __half* __restrict__ lh)
{
    __shared__ float t[32][33];
    const int b = blockIdx.x;

    if (b < CVT_BLKS) {
        int i = b * 256 + threadIdx.x;
        float4 v = ((const float4*)x)[i];
        __half2* O = (__half2*)xh;
        O[i*2]   = __floats2half2_rn(v.x, v.y);
        O[i*2+1] = __floats2half2_rn(v.z, v.w);
        return;
    }

    // transpose job
    const int tb   = b - CVT_BLKS;          // 0..2047
    const int job  = tb >> 10;              // 0: W, 1: leaf
    const int lb   = tb & 1023;
    const float* in  = job ? leaf : Wg;
    __half* outT     = job ? lh : wh;
    const int Nin    = job ? N_OUT : N_GATE;

    const int k0 = (lb & 31) * 32, n0 = (lb >> 5) * 32;
    const int xx = threadIdx.x & 31, yy = threadIdx.x >> 5;
    #pragma unroll
    for (int i = 0; i < 32; i += 8) {
        int n = n0 + xx;
        t[yy + i][xx] = (n < Nin) ? in[(size_t)(k0 + yy + i) * Nin + n] : 0.f;
    }
    __syncthreads();
    #pragma unroll
    for (int i = 0; i < 32; i += 8) {
        int n = n0 + yy + i, k = k0 + xx;
        outT[(size_t)n * 1024 + k] = __float2half_rn(t[xx][yy + i]);
    }
}

// ---------------------------------------------------------------------------
// Tree path-product -> probs as fp16.
// ---------------------------------------------------------------------------
__global__ void __launch_bounds__(256)
tree_kernel()
{
    __shared__ float sp[2][1024];
    const int half = threadIdx.x >> 7;
    const int t    = threadIdx.x & 127;
    const int s    = blockIdx.x * 2 + half;

    const float* prow = g_p + (size_t)s * 1024;
    #pragma unroll
    for (int i = 0; i < 8; i++) {
        int idx = t + i * 128;
        if (idx < N_GATE) sp[half][idx] = prow[idx];
    }
    __syncthreads();

    const float* pr = sp[half];
    const int base = t * 8;

    float pref = 1.0f;
    #pragma unroll
    for (int k = 0; k < 7; k++) {
        int node = (1 << k) - 1 + (base >> (10 - k));
        int bit  = (base >> (9 - k)) & 1;
        float pv = pr[node];
        pref *= bit ? pv : (1.0f - pv);
    }
    float p7 = pr[127 + (base >> 3)];
    float p8[2];
    p8[0] = pr[255 + (base >> 2) + 0];
    p8[1] = pr[255 + (base >> 2) + 1];
    float p9[4];
    #pragma unroll
    for (int i = 0; i < 4; i++) p9[i] = pr[511 + (base >> 1) + i];

    __align__(16) __half H[8];
    #pragma unroll
    for (int j = 0; j < 8; j++) {
        int b2 = (j >> 2) & 1, b1 = (j >> 1) & 1, b0 = j & 1;
        float v = pref * (b2 ? p7 : (1.0f - p7));
        float q8 = p8[b2];
        v *= b1 ? q8 : (1.0f - q8);
        float q9 = p9[j >> 1];
        v *= b0 ? q9 : (1.0f - q9);
        H[j] = __float2half_rn(v);
    }
    *(uint4*)(g_ph + (size_t)s * 1024 + base) = *(uint4*)H;
}

// ---------------------------------------------------------------------------
extern "C" void kernel_launch(void* const* d_in, const int* in_sizes, int n_in,
                              void* d_out, int out_size)
{
    const float* x    = (const float*)d_in[0];
    const float* Wg   = (const float*)d_in[1];
    const float* bg   = (const float*)d_in[2];
    const float* leaf = (const float*)d_in[3];
    float* out = (float*)d_out;

    float *p_ptr;
    __half *xh, *ph, *wh, *lh;
    cudaGetSymbolAddress((void**)&p_ptr, g_p);
    cudaGetSymbolAddress((void**)&xh, g_xh);
    cudaGetSymbolAddress((void**)&ph, g_ph);
    cudaGetSymbolAddress((void**)&wh, g_wh);
    cudaGetSymbolAddress((void**)&lh, g_lh);

    cudaFuncSetAttribute(hmma_gemm<1>, cudaFuncAttributeMaxDynamicSharedMemorySize, SMEM_TOTAL);
    cudaFuncSetAttribute(hmma_gemm<0>, cudaFuncAttributeMaxDynamicSharedMemorySize, SMEM_TOTAL);

    // fused prep: convert x + transpose/convert both weight matrices
    prep_kernel<<<CVT_BLKS + 2048, 256>>>(x, Wg, leaf, xh, wh, lh);

    // GEMM1 + sigmoid -> g_p
    {
        dim3 grid(1024 / BN, M_DIM / BM);   // (8, 128)
        hmma_gemm<1><<<grid, 256, SMEM_TOTAL>>>(xh, wh, bg, p_ptr);
    }

    // tree products -> probs fp16
    tree_kernel<<<M_DIM / 2, 256>>>();

    // GEMM2 -> out
    {
        dim3 grid(1024 / BN, M_DIM / BM);   // (8, 128)
        hmma_gemm<0><<<grid, 256, SMEM_TOTAL>>>(ph, lh, nullptr, out);
    }
}

// round 17
// speedup vs baseline: 1.0412x; 1.0071x over previous
#include <cuda_runtime.h>
#include <cuda_fp16.h>
#include <cstdint>
#include <cstddef>

// ===========================================================================
// TreeModel via single-pass fp16 HMMA GEMMs (fp32 accumulate).
// R16: R15 + Programmatic Dependent Launch (PDL) across prep->GEMM1->tree->GEMM2
// to overlap launch latency + prologues with predecessor tails.
// ===========================================================================

#define M_DIM   16384
#define K_DIM   1024
#define N_GATE  1023
#define N_OUT   1000

#define BM      128
#define BN      128
#define BK      64          // 64 fp16 = 128B rows (swizzled)
#define NCHUNKS 16          // 1024 / 64
#define STAGES  3

#define A_BYTES (BM * BK * 2)        // 16 KB
#define B_BYTES (BN * BK * 2)        // 16 KB
#define STG_BYTES (A_BYTES + B_BYTES)
#define TILES_BYTES (STAGES * STG_BYTES)          // 96 KB
#define SMEM_TOTAL  (TILES_BYTES + 64)

// ---- scratch (static device allocations) ----
__device__ float   g_p  [(size_t)M_DIM * 1024];   // gate probabilities (f32)
__device__ __half  g_xh [(size_t)M_DIM * 1024];   // fp16(x)
__device__ __half  g_ph [(size_t)M_DIM * 1024];   // fp16(probs)
__device__ __half  g_wh [1024 * 1024];            // W_gate^T fp16
__device__ __half  g_lh [1024 * 1024];            // leaf^T fp16

__device__ __forceinline__ uint32_t smem_u32(const void* p) {
    uint32_t a;
    asm("{ .reg .u64 t; cvta.to.shared.u64 t, %1; cvt.u32.u64 %0, t; }" : "=r"(a) : "l"(p));
    return a;
}
__device__ __forceinline__ uint32_t elect_one() {
    uint32_t r;
    asm volatile("{\n\t.reg .pred p;\n\telect.sync _|p, 0xFFFFFFFF;\n\tselp.b32 %0, 1, 0, p;\n\t}" : "=r"(r));
    return r;
}
__device__ __forceinline__ void cp16(uint32_t saddr, const void* gaddr) {
    asm volatile("cp.async.cg.shared.global [%0], [%1], 16;" :: "r"(saddr), "l"(gaddr));
}
__device__ __forceinline__ void ldsm_x4(uint32_t& r0, uint32_t& r1, uint32_t& r2, uint32_t& r3,
                                        uint32_t addr) {
    asm volatile("ldmatrix.sync.aligned.m8n8.x4.shared.b16 {%0,%1,%2,%3}, [%4];"
                 : "=r"(r0), "=r"(r1), "=r"(r2), "=r"(r3) : "r"(addr));
}
__device__ __forceinline__ void mma16816(float* c, const uint32_t* a, uint32_t b0, uint32_t b1) {
    asm("mma.sync.aligned.m16n8k16.row.col.f32.f16.f16.f32 "
        "{%0,%1,%2,%3}, {%4,%5,%6,%7}, {%8,%9}, {%0,%1,%2,%3};"
        : "+f"(c[0]), "+f"(c[1]), "+f"(c[2]), "+f"(c[3])
        : "r"(a[0]), "r"(a[1]), "r"(a[2]), "r"(a[3]), "r"(b0), "r"(b1));
}
// PDL device helpers (safe no-ops when launched without the attribute)
__device__ __forceinline__ void pdl_wait()    { cudaGridDependencySynchronize(); }
__device__ __forceinline__ void pdl_trigger() { cudaTriggerProgrammaticLaunchCompletion(); }

// ---- mbarrier helpers ----
#define MBAR_INIT(a, c) \
    asm volatile("mbarrier.init.shared.b64 [%0], %1;" :: "r"(a), "r"(c) : "memory")
#define MBAR_ARRIVE(a) \
    asm volatile("mbarrier.arrive.shared.b64 _, [%0];" :: "r"(a) : "memory")
#define CP_ASYNC_MBAR_ARRIVE(a) \
    asm volatile("cp.async.mbarrier.arrive.noinc.shared::cta.b64 [%0];" :: "r"(a) : "memory")
#define MBAR_WAIT(a, par) do {                                                   \
    uint32_t _m = (a); uint32_t _p = (par); uint32_t _d;                         \
    asm volatile("{\n\t.reg .pred p;\n\t"                                        \
        "mbarrier.try_wait.parity.acquire.cta.shared::cta.b64 p, [%1], %2;\n\t"  \
        "selp.b32 %0, 1, 0, p;\n\t}" : "=r"(_d) : "r"(_m), "r"(_p) : "memory");  \
    if (!_d) {                                                                   \
        asm volatile("{\n\t.reg .pred P1;\n\t"                                   \
            "WL_%=:\n\t"                                                         \
            "mbarrier.try_wait.parity.acquire.cta.shared::cta.b64 P1, [%0], %1, 0x989680;\n\t" \
            "@P1 bra.uni WD_%=;\n\t"                                             \
            "bra.uni WL_%=;\n\t"                                                 \
            "WD_%=:\n\t}" :: "r"(_m), "r"(_p) : "memory");                       \
    } } while (0)

// ---------------------------------------------------------------------------
// EPI=1: sigmoid(acc + bias) -> f32 C (ldc=1024)
// EPI=0: acc -> f32 C (ldc=N_OUT, guard col < N_OUT)
// ---------------------------------------------------------------------------
template<int EPI>
__global__ void __launch_bounds__(256, 2)
hmma_gemm(const __half* __restrict__ A, const __half* __restrict__ B,
          const float* __restrict__ bias, float* __restrict__ C)
{
    extern __shared__ char smem[];
    const uint32_t sbase = smem_u32(smem);
    const uint32_t mbase = sbase + TILES_BYTES;   // full[s] +s*16, empty[s] +s*16+8
    const int tid  = threadIdx.x;
    const int lane = tid & 31;
    const int wid  = tid >> 5;
    const int wm   = wid >> 1;          // 0..3
    const int wn   = wid & 1;           // 0..1
    const int m0w  = wm * 32;
    const int n0w  = wn * 64;
    const int bm0  = blockIdx.y * BM;
    const int bn0  = blockIdx.x * BN;

    if (tid == 0) {
        #pragma unroll
        for (int s = 0; s < STAGES; s++) {
            MBAR_INIT(mbase + s * 16, 256);       // full: 256 cp-group arrivals
            MBAR_INIT(mbase + s * 16 + 8, 8);     // empty: 8 per-warp arrivals
        }
    }
    __syncthreads();

    // ---- hoisted loader state: 4 swizzled smem offsets + 4 A ptrs + uniform delta
    uint32_t swOff[4];
    const char* gA[4];
    const ptrdiff_t bd = ((const char*)B - (const char*)A)
                       + (ptrdiff_t)(bn0 - bm0) * (K_DIM * 2);
    #pragma unroll
    for (int i = 0; i < 4; i++) {
        int idx = i * 256 + tid;                 // 0..1023
        int row = idx >> 3;                      // 0..127
        int ch  = idx & 7;                       // 16B chunk in row
        uint32_t col = (uint32_t)ch * 16;
        swOff[i] = (uint32_t)row * 128 + (col ^ (((uint32_t)row & 7u) << 4));
        gA[i] = (const char*)(A + (size_t)(bm0 + row) * K_DIM) + ch * 16;
    }

    // ldmatrix addressing: addr = rowBase + ((lh*16 + ks*32) ^ swmask)
    const int lr = lane & 15;
    const int lh = lane >> 4;
    const uint32_t sw = ((uint32_t)lr & 7u) << 4;
    uint32_t colX[4];
    #pragma unroll
    for (int ks = 0; ks < 4; ks++)
        colX[ks] = (((uint32_t)lh * 16) + (uint32_t)ks * 32) ^ sw;
    uint32_t aRow[2], bRow[4];
    #pragma unroll
    for (int mt = 0; mt < 2; mt++) aRow[mt] = (uint32_t)(m0w + mt * 16 + lr) * 128;
    #pragma unroll
    for (int p = 0; p < 4; p++)    bRow[p]  = (uint32_t)(n0w + p * 16 + lr) * 128;

    float acc[2][8][4];
    #pragma unroll
    for (int mt = 0; mt < 2; mt++)
        #pragma unroll
        for (int nt = 0; nt < 8; nt++)
            #pragma unroll
            for (int q = 0; q < 4; q++) acc[mt][nt][q] = 0.f;

    // wait for predecessor's data (PDL); no-op on non-PDL launches
    pdl_wait();

    // producer cursor (stage 0, phase 1): first empty-waits pass immediately
    int pst = 0, pph = 1;
    #pragma unroll
    for (int pc = 0; pc < 2; pc++) {
        const uint32_t sa = sbase + (uint32_t)pst * STG_BYTES;
        const uint32_t sb = sa + A_BYTES;
        #pragma unroll
        for (int i = 0; i < 4; i++) {
            cp16(sa + swOff[i], gA[i]);
            cp16(sb + swOff[i], gA[i] + bd);
            gA[i] += BK * 2;
        }
        CP_ASYNC_MBAR_ARRIVE(mbase + pst * 16);
        if (++pst == STAGES) { pst = 0; pph ^= 1; }
    }

    int cst = 0, cph = 0;

    #pragma unroll 1
    for (int c = 0; c < NCHUNKS; c++) {
        MBAR_WAIT(mbase + cst * 16, (uint32_t)cph);          // stage cst full

        if (c + 2 < NCHUNKS) {
            MBAR_WAIT(mbase + pst * 16 + 8, (uint32_t)pph);  // stage pst empty
            const uint32_t sa = sbase + (uint32_t)pst * STG_BYTES;
            const uint32_t sb = sa + A_BYTES;
            #pragma unroll
            for (int i = 0; i < 4; i++) {
                cp16(sa + swOff[i], gA[i]);
                cp16(sb + swOff[i], gA[i] + bd);
                gA[i] += BK * 2;
            }
            CP_ASYNC_MBAR_ARRIVE(mbase + pst * 16);
            if (++pst == STAGES) { pst = 0; pph ^= 1; }
        }

        const uint32_t sa = sbase + (uint32_t)cst * STG_BYTES;
        const uint32_t sb = sa + A_BYTES;

        #pragma unroll
        for (int ks = 0; ks < 4; ks++) {
            uint32_t a[2][4];
            #pragma unroll
            for (int mt = 0; mt < 2; mt++)
                ldsm_x4(a[mt][0], a[mt][1], a[mt][2], a[mt][3], sa + aRow[mt] + colX[ks]);
            uint32_t b[8][2];
            #pragma unroll
            for (int p = 0; p < 4; p++) {
                uint32_t r0, r1, r2, r3;
                ldsm_x4(r0, r1, r2, r3, sb + bRow[p] + colX[ks]);
                b[p*2][0] = r0; b[p*2][1] = r2;
                b[p*2+1][0] = r1; b[p*2+1][1] = r3;
            }
            #pragma unroll
            for (int mt = 0; mt < 2; mt++)
                #pragma unroll
                for (int nt = 0; nt < 8; nt++)
                    mma16816(acc[mt][nt], a[mt], b[nt][0], b[nt][1]);
        }

        // warp-synchronous at this point: one elected arrive per warp
        if (elect_one())
            MBAR_ARRIVE(mbase + cst * 16 + 8);               // done reading stage cst
        if (++cst == STAGES) { cst = 0; cph ^= 1; }
    }

    // epilogue
    const int gq = lane >> 2;
    const int tq = lane & 3;
    #pragma unroll
    for (int mt = 0; mt < 2; mt++) {
        #pragma unroll
        for (int nt = 0; nt < 8; nt++) {
            const int col = bn0 + n0w + nt * 8 + tq * 2;
            const int r0  = bm0 + m0w + mt * 16 + gq;
            float v0 = acc[mt][nt][0], v1 = acc[mt][nt][1];
            float v2 = acc[mt][nt][2], v3 = acc[mt][nt][3];
            if (EPI == 1) {
                float b0 = (col     < N_GATE) ? bias[col]     : 0.f;
                float b1 = (col + 1 < N_GATE) ? bias[col + 1] : 0.f;
                v0 = 1.f / (1.f + __expf(-(v0 + b0)));
                v1 = 1.f / (1.f + __expf(-(v1 + b1)));
                v2 = 1.f / (1.f + __expf(-(v2 + b0)));
                v3 = 1.f / (1.f + __expf(-(v3 + b1)));
                *(float2*)(C + (size_t)r0 * 1024 + col)       = make_float2(v0, v1);
                *(float2*)(C + (size_t)(r0 + 8) * 1024 + col) = make_float2(v2, v3);
            } else {
                if (col + 1 < N_OUT) {
                    *(float2*)(C + (size_t)r0 * N_OUT + col)       = make_float2(v0, v1);
                    *(float2*)(C + (size_t)(r0 + 8) * N_OUT + col) = make_float2(v2, v3);
                } else if (col < N_OUT) {
                    C[(size_t)r0 * N_OUT + col]       = v0;
                    C[(size_t)(r0 + 8) * N_OUT + col] = v2;
                }
            }
        }
    }
    pdl_trigger();
}

// ---------------------------------------------------------------------------
// Fused prep: blocks [0, CVT_BLKS): x f32->fp16
//             [CVT_BLKS, +1024): transpose+cvt W_gate
//             [CVT_BLKS+1024, +2048): transpose+cvt leaf_logits
// ---------------------------------------------------------------------------
#define CVT_BLKS ((M_DIM * K_DIM / 4) / 256)   // 16384

__global__ void __launch_bounds__(256)
prep_kernel(const float* __restrict__ x,
            const float* __restrict__ Wg,
            const float* __restrict__ leaf,
            __half* __restrict__ xh,
            __half* __restrict__ wh,
            __half* __restrict__ lh)
{
    __shared__ float t[32][33];
    const int b = blockIdx.x;

    if (b < CVT_BLKS) {
        int i = b * 256 + threadIdx.x;
        float4 v = ((const float4*)x)[i];
        __half2* O = (__half2*)xh;
        O[i*2]   = __floats2half2_rn(v.x, v.y);
        O[i*2+1] = __floats2half2_rn(v.z, v.w);
        pdl_trigger();
        return;
    }

    // transpose job
    const int tb   = b - CVT_BLKS;          // 0..2047
    const int job  = tb >> 10;              // 0: W, 1: leaf
    const int lb   = tb & 1023;
    const float* in  = job ? leaf : Wg;
    __half* outT     = job ? lh : wh;
    const int Nin    = job ? N_OUT : N_GATE;

    const int k0 = (lb & 31) * 32, n0 = (lb >> 5) * 32;
    const int xx = threadIdx.x & 31, yy = threadIdx.x >> 5;
    #pragma unroll
    for (int i = 0; i < 32; i += 8) {
        int n = n0 + xx;
        t[yy + i][xx] = (n < Nin) ? in[(size_t)(k0 + yy + i) * Nin + n] : 0.f;
    }
    __syncthreads();
    #pragma unroll
    for (int i = 0; i < 32; i += 8) {
        int n = n0 + yy + i, k = k0 + xx;
        outT[(size_t)n * 1024 + k] = __float2half_rn(t[xx][yy + i]);
    }
    pdl_trigger();
}

// ---------------------------------------------------------------------------
// Tree path-product -> probs as fp16.
// ---------------------------------------------------------------------------
__global__ void __launch_bounds__(256)
tree_kernel()
{
    __shared__ float sp[2][1024];
    const int half = threadIdx.x >> 7;
    const int t    = threadIdx.x & 127;
    const int s    = blockIdx.x * 2 + half;

    pdl_wait();   // g_p produced by GEMM1

    const float* prow = g_p + (size_t)s * 1024;
    #pragma unroll
    for (int i = 0; i < 8; i++) {
        int idx = t + i * 128;
        if (idx < N_GATE) sp[half][idx] = prow[idx];
    }
    __syncthreads();

    const float* pr = sp[half];
    const int base = t * 8;

    float pref = 1.0f;
    #pragma unroll
    for (int k = 0; k < 7; k++) {
        int node = (1 << k) - 1 + (base >> (10 - k));
        int bit  = (base >> (9 - k)) & 1;
        float pv = pr[node];
        pref *= bit ? pv : (1.0f - pv);
    }
    float p7 = pr[127 + (base >> 3)];
    float p8[2];
    p8[0] = pr[255 + (base >> 2) + 0];
    p8[1] = pr[255 + (base >> 2) + 1];
    float p9[4];
    #pragma unroll
    for (int i = 0; i < 4; i++) p9[i] = pr[511 + (base >> 1) + i];

    __align__(16) __half H[8];
    #pragma unroll
    for (int j = 0; j < 8; j++) {
        int b2 = (j >> 2) & 1, b1 = (j >> 1) & 1, b0 = j & 1;
        float v = pref * (b2 ? p7 : (1.0f - p7));
        float q8 = p8[b2];
        v *= b1 ? q8 : (1.0f - q8);
        float q9 = p9[j >> 1];
        v *= b0 ? q9 : (1.0f - q9);
        H[j] = __float2half_rn(v);
    }
    *(uint4*)(g_ph + (size_t)s * 1024 + base) = *(uint4*)H;
    pdl_trigger();
}

// ---------------------------------------------------------------------------
extern "C" void kernel_launch(void* const* d_in, const int* in_sizes, int n_in,
                              void* d_out, int out_size)
{
    const float* x    = (const float*)d_in[0];
    const float* Wg   = (const float*)d_in[1];
    const float* bg   = (const float*)d_in[2];
    const float* leaf = (const float*)d_in[3];
    float* out = (float*)d_out;

    float *p_ptr;
    __half *xh, *ph, *wh, *lh;
    cudaGetSymbolAddress((void**)&p_ptr, g_p);
    cudaGetSymbolAddress((void**)&xh, g_xh);
    cudaGetSymbolAddress((void**)&ph, g_ph);
    cudaGetSymbolAddress((void**)&wh, g_wh);
    cudaGetSymbolAddress((void**)&lh, g_lh);

    cudaFuncSetAttribute(hmma_gemm<1>, cudaFuncAttributeMaxDynamicSharedMemorySize, SMEM_TOTAL);
    cudaFuncSetAttribute(hmma_gemm<0>, cudaFuncAttributeMaxDynamicSharedMemorySize, SMEM_TOTAL);

    cudaLaunchAttribute pdlAttr[1];
    pdlAttr[0].id = cudaLaunchAttributeProgrammaticStreamSerialization;
    pdlAttr[0].val.programmaticStreamSerializationAllowed = 1;

    // prep: plain launch (head of chain)
    prep_kernel<<<CVT_BLKS + 2048, 256>>>(x, Wg, leaf, xh, wh, lh);

    // GEMM1 + sigmoid -> g_p  (PDL on prep)
    {
        cudaLaunchConfig_t cfg = {};
        cfg.gridDim = dim3(1024 / BN, M_DIM / BM);
        cfg.blockDim = dim3(256);
        cfg.dynamicSmemBytes = SMEM_TOTAL;
        cfg.stream = 0;
        cfg.attrs = pdlAttr;
        cfg.numAttrs = 1;
        cudaLaunchKernelEx(&cfg, hmma_gemm<1>, (const __half*)xh, (const __half*)wh,
                           (const float*)bg, (float*)p_ptr);
    }

    // tree -> probs fp16  (PDL on GEMM1)
    {
        cudaLaunchConfig_t cfg = {};
        cfg.gridDim = dim3(M_DIM / 2);
        cfg.blockDim = dim3(256);
        cfg.dynamicSmemBytes = 0;
        cfg.stream = 0;
        cfg.attrs = pdlAttr;
        cfg.numAttrs = 1;
        cudaLaunchKernelEx(&cfg, tree_kernel);
    }

    // GEMM2 -> out  (PDL on tree)
    {
        cudaLaunchConfig_t cfg = {};
        cfg.gridDim = dim3(1024 / BN, M_DIM / BM);
        cfg.blockDim = dim3(256);
        cfg.dynamicSmemBytes = SMEM_TOTAL;
        cfg.stream = 0;
        cfg.attrs = pdlAttr;
        cfg.numAttrs = 1;
        cudaLaunchKernelEx(&cfg, hmma_gemm<0>, (const __half*)ph, (const __half*)lh,
                           (const float*)nullptr, (float*)out);
    }
}